// round 15
// baseline (speedup 1.0000x reference)
#include <cuda_runtime.h>
#include <cuda_bf16.h>
#include <cuda_fp16.h>
#include <cstdint>

#define N_NODES 50000
#define N_EDGES 800000

// Scratch (__device__ globals; no allocation). NEVER pass these from host code:
// on GB300 (HMM/ATS) the host shadow symbol is GPU-dereferenceable and the kernel
// silently reads host memory over C2C (Round 9: 170->477us regression).
__device__ __half g_h16[N_NODES * 128];  // GEMM output per layer, dinv-scaled, fp16
__device__ float g_agg[N_NODES * 128];   // aggregation output (layers 1,2), fp32
__device__ int   g_deg[N_NODES];
__device__ float g_dinv[N_NODES];
__device__ int   g_off[N_NODES];         // CSR segment start (by dst; unordered alloc)
__device__ int   g_cursor[N_NODES];      // fill cursors
__device__ int   g_csr_src[N_EDGES];     // src ids grouped by dst
__device__ int   g_total;                // bump allocator
// Presplit weights, n-major: WT[n*128 + k]
__device__ __nv_bfloat16 g_W1hi[128 * 128], g_W1lo[128 * 128];
__device__ __nv_bfloat16 g_W2hi[128 * 128], g_W2lo[128 * 128];
__device__ __nv_bfloat16 g_W3hi[64 * 128],  g_W3lo[64 * 128];

template<int LAYER>
__device__ __forceinline__ __nv_bfloat16* w_hi() {
    return LAYER == 1 ? g_W1hi : (LAYER == 2 ? g_W2hi : g_W3hi);
}
template<int LAYER>
__device__ __forceinline__ __nv_bfloat16* w_lo() {
    return LAYER == 1 ? g_W1lo : (LAYER == 2 ? g_W2lo : g_W3lo);
}

// ---------------- fp32 -> bf16 hi/lo split helpers ----------------

__device__ __forceinline__ void split8(const float* v, uint4& hi, uint4& lo) {
    uint32_t h[4], l[4];
#pragma unroll
    for (int j = 0; j < 4; j++) {
        __nv_bfloat16 h0 = __float2bfloat16(v[2 * j]);
        __nv_bfloat16 h1 = __float2bfloat16(v[2 * j + 1]);
        float f0 = __bfloat162float(h0), f1 = __bfloat162float(h1);
        __nv_bfloat162 hh = __halves2bfloat162(h0, h1);
        __nv_bfloat162 ll = __halves2bfloat162(__float2bfloat16(v[2 * j] - f0),
                                               __float2bfloat16(v[2 * j + 1] - f1));
        h[j] = *reinterpret_cast<uint32_t*>(&hh);
        l[j] = *reinterpret_cast<uint32_t*>(&ll);
    }
    hi = make_uint4(h[0], h[1], h[2], h[3]);
    lo = make_uint4(l[0], l[1], l[2], l[3]);
}

template<int N>
__device__ __forceinline__ void wsplit_work(const float* __restrict__ W,
                                            __nv_bfloat16* hi, __nv_bfloat16* lo, int idx) {
    int n = idx % N;
    int kg = idx / N;
    float v[8];
#pragma unroll
    for (int j = 0; j < 8; j++) v[j] = W[(size_t)(kg * 8 + j) * N + n];
    uint4 h, l;
    split8(v, h, l);
    *(uint4*)&hi[n * 128 + kg * 8] = h;
    *(uint4*)&lo[n * 128 + kg * 8] = l;
}

// ---------------- fused setup: deg init + weight presplit (one launch) ----------------

__global__ void setup_kernel(const float* __restrict__ W1, const float* __restrict__ W2,
                             const float* __restrict__ W3) {
    const int bid = blockIdx.x;
    const int tid = threadIdx.x;
    if (bid < 196) {
        int i = bid * 256 + tid;
        if (i == 0) g_total = 0;
        if (i < N_NODES) g_deg[i] = 1;   // self loop
    } else {
        int idx = (bid - 196) * 256 + tid;          // 0..5119
        if (idx < 2048) {
            wsplit_work<128>(W1, g_W1hi, g_W1lo, idx);
        } else if (idx < 4096) {
            wsplit_work<128>(W2, g_W2hi, g_W2lo, idx - 2048);
        } else if (idx < 5120) {
            wsplit_work<64>(W3, g_W3hi, g_W3lo, idx - 4096);
        }
    }
}

// ---------------- degree count: 8 edges/thread ----------------

__global__ void deg_count_kernel(const int4* __restrict__ dst4) {
    int i = blockIdx.x * blockDim.x + threadIdx.x;
    if (i < N_EDGES / 8) {
        int4 d0 = dst4[2 * i];
        int4 d1 = dst4[2 * i + 1];
        atomicAdd(&g_deg[d0.x], 1);
        atomicAdd(&g_deg[d0.y], 1);
        atomicAdd(&g_deg[d0.z], 1);
        atomicAdd(&g_deg[d0.w], 1);
        atomicAdd(&g_deg[d1.x], 1);
        atomicAdd(&g_deg[d1.y], 1);
        atomicAdd(&g_deg[d1.z], 1);
        atomicAdd(&g_deg[d1.w], 1);
    }
}

// dinv + CSR segment allocation (merged)
__global__ void dinv_alloc_kernel() {
    int i = blockIdx.x * blockDim.x + threadIdx.x;
    int lane = threadIdx.x & 31;
    int deg = (i < N_NODES) ? g_deg[i] : 1;
    if (i < N_NODES) g_dinv[i] = rsqrtf((float)deg);
    int cnt = (i < N_NODES) ? (deg - 1) : 0;
    int incl = cnt;
#pragma unroll
    for (int off = 1; off < 32; off <<= 1) {
        int t = __shfl_up_sync(0xffffffffu, incl, off);
        if (lane >= off) incl += t;
    }
    int total = __shfl_sync(0xffffffffu, incl, 31);
    int base = 0;
    if (lane == 0) base = atomicAdd(&g_total, total);
    base = __shfl_sync(0xffffffffu, base, 0);
    if (i < N_NODES) {
        int beg = base + incl - cnt;
        g_off[i] = beg;
        g_cursor[i] = beg;
    }
}

// CSR fill: 8 edges/thread, independent atomic chains for MLP
__global__ void fill_kernel(const int4* __restrict__ src4, const int4* __restrict__ dst4) {
    int i = blockIdx.x * blockDim.x + threadIdx.x;
    if (i < N_EDGES / 8) {
        int4 s0 = src4[2 * i];
        int4 s1 = src4[2 * i + 1];
        int4 d0 = dst4[2 * i];
        int4 d1 = dst4[2 * i + 1];
        int p0 = atomicAdd(&g_cursor[d0.x], 1);
        int p1 = atomicAdd(&g_cursor[d0.y], 1);
        int p2 = atomicAdd(&g_cursor[d0.z], 1);
        int p3 = atomicAdd(&g_cursor[d0.w], 1);
        int p4 = atomicAdd(&g_cursor[d1.x], 1);
        int p5 = atomicAdd(&g_cursor[d1.y], 1);
        int p6 = atomicAdd(&g_cursor[d1.z], 1);
        int p7 = atomicAdd(&g_cursor[d1.w], 1);
        g_csr_src[p0] = s0.x;
        g_csr_src[p1] = s0.y;
        g_csr_src[p2] = s0.z;
        g_csr_src[p3] = s0.w;
        g_csr_src[p4] = s1.x;
        g_csr_src[p5] = s1.y;
        g_csr_src[p6] = s1.z;
        g_csr_src[p7] = s1.w;
    }
}

// ================= bf16x3 mma.sync GEMM =================
// g_h16[M,N] = fp16( ( act(X[M,128]) @ W[128,N] ) * dinv[row] )
// BM=64 for 2 CTAs/SM (smem 104.4KB @ N=128).

__device__ __forceinline__ uint32_t smem_u32(const void* p) {
    return (uint32_t)__cvta_generic_to_shared(p);
}

__device__ __forceinline__ void ldsm4(uint32_t* r, uint32_t addr) {
    asm volatile("ldmatrix.sync.aligned.m8n8.x4.shared.b16 {%0,%1,%2,%3}, [%4];"
                 : "=r"(r[0]), "=r"(r[1]), "=r"(r[2]), "=r"(r[3]) : "r"(addr));
}

__device__ __forceinline__ void mma16816(float* d, const uint32_t* a,
                                         uint32_t b0, uint32_t b1) {
    asm volatile(
        "mma.sync.aligned.m16n8k16.row.col.f32.bf16.bf16.f32 "
        "{%0,%1,%2,%3}, {%4,%5,%6,%7}, {%8,%9}, {%0,%1,%2,%3};"
        : "+f"(d[0]), "+f"(d[1]), "+f"(d[2]), "+f"(d[3])
        : "r"(a[0]), "r"(a[1]), "r"(a[2]), "r"(a[3]), "r"(b0), "r"(b1));
}

// Block: 64(M) x N, K=128 resident. 8 warps in 2x4; warp tile 32 x N/4.
template<int N, bool RELU, bool FROM_AGG, int LAYER>
__global__ void __launch_bounds__(256) gemm_mma_kernel(const float* __restrict__ X, int M) {
    constexpr int K = 128, BM = 64, SB = 136;
    constexpr int A_ELE = BM * SB;
    constexpr int B_ELE = N * SB;
    constexpr int NA = N / 32;                   // n-atoms (m16n8) per warp (4 or 2)

    extern __shared__ __nv_bfloat16 sm[];
    __nv_bfloat16* Ahi = sm;
    __nv_bfloat16* Alo = sm + A_ELE;
    __nv_bfloat16* Bhi = sm + 2 * A_ELE;
    __nv_bfloat16* Blo = sm + 2 * A_ELE + B_ELE;

    const float* __restrict__ Xp = FROM_AGG ? (const float*)g_agg : X;
    const __nv_bfloat16* __restrict__ WThi = w_hi<LAYER>();
    const __nv_bfloat16* __restrict__ WTlo = w_lo<LAYER>();
    const int tid = threadIdx.x;
    const int m0 = blockIdx.x * BM;

    // ---- copy presplit W into smem ----
#pragma unroll
    for (int i = tid; i < N * 16; i += 256) {
        int n = i >> 4;
        int k0 = (i & 15) * 8;
        *(uint4*)&Bhi[n * SB + k0] = *(const uint4*)&WThi[n * 128 + k0];
        *(uint4*)&Blo[n * SB + k0] = *(const uint4*)&WTlo[n * 128 + k0];
    }

    // ---- load + split X: thread = (row = tid>>2, quarter kh = (tid&3)*32) ----
    {
        const int row = tid >> 2;
        const int kh = (tid & 3) * 32;
        const int gm = m0 + row;
        float v[8];
#pragma unroll
        for (int c0 = 0; c0 < 32; c0 += 8) {
            if (gm < M) {
                float4 a = *(const float4*)&Xp[(size_t)gm * K + kh + c0];
                float4 b = *(const float4*)&Xp[(size_t)gm * K + kh + c0 + 4];
                v[0] = a.x; v[1] = a.y; v[2] = a.z; v[3] = a.w;
                v[4] = b.x; v[5] = b.y; v[6] = b.z; v[7] = b.w;
                if (RELU) {
#pragma unroll
                    for (int j = 0; j < 8; j++) v[j] = fmaxf(v[j], 0.f);
                }
            } else {
#pragma unroll
                for (int j = 0; j < 8; j++) v[j] = 0.f;
            }
            uint4 hi, lo;
            split8(v, hi, lo);
            *(uint4*)&Ahi[row * SB + kh + c0] = hi;
            *(uint4*)&Alo[row * SB + kh + c0] = lo;
        }
    }
    __syncthreads();

    const uint32_t aHi = smem_u32(Ahi), aLo = smem_u32(Alo);
    const uint32_t bHi = smem_u32(Bhi), bLo = smem_u32(Blo);
    const int wid = tid >> 5, lane = tid & 31;
    const int mb = (wid & 1) * 32;               // warp row base (2 rows of warps)
    const int nb = (wid >> 1) * (N / 4);         // warp col base (4 cols of warps)

    float acc[2][NA][4];
#pragma unroll
    for (int mi = 0; mi < 2; mi++)
#pragma unroll
        for (int ni = 0; ni < NA; ni++)
#pragma unroll
            for (int j = 0; j < 4; j++) acc[mi][ni][j] = 0.f;

    const int l3 = lane >> 3;
    const uint32_t offA = (uint32_t)((mb + (lane & 15)) * SB + ((lane >> 4) << 3)) * 2;
    const uint32_t offB = (uint32_t)((nb + ((l3 >> 1) << 3) + (lane & 7)) * SB + ((l3 & 1) << 3)) * 2;

#pragma unroll
    for (int ks = 0; ks < 8; ks++) {
        const uint32_t kofs = (uint32_t)(ks * 16 * 2);
        uint32_t ah[2][4], al[2][4];
        ldsm4(ah[0], aHi + offA + kofs);
        ldsm4(ah[1], aHi + offA + kofs + 16 * SB * 2);
        ldsm4(al[0], aLo + offA + kofs);
        ldsm4(al[1], aLo + offA + kofs + 16 * SB * 2);

        uint32_t bh[NA][2], bl[NA][2];
#pragma unroll
        for (int nq = 0; nq < NA / 2; nq++) {
            uint32_t r[4];
            ldsm4(r, bHi + offB + kofs + nq * 16 * SB * 2);
            bh[2 * nq][0] = r[0]; bh[2 * nq][1] = r[1];
            bh[2 * nq + 1][0] = r[2]; bh[2 * nq + 1][1] = r[3];
            ldsm4(r, bLo + offB + kofs + nq * 16 * SB * 2);
            bl[2 * nq][0] = r[0]; bl[2 * nq][1] = r[1];
            bl[2 * nq + 1][0] = r[2]; bl[2 * nq + 1][1] = r[3];
        }

#pragma unroll
        for (int mi = 0; mi < 2; mi++)
#pragma unroll
            for (int ni = 0; ni < NA; ni++) {
                mma16816(acc[mi][ni], ah[mi], bh[ni][0], bh[ni][1]);
                mma16816(acc[mi][ni], ah[mi], bl[ni][0], bl[ni][1]);
                mma16816(acc[mi][ni], al[mi], bh[ni][0], bh[ni][1]);
            }
    }

    // ---- epilogue: scale by dinv[row], convert fp16, store ----
    const int g = lane >> 2, tg = lane & 3;
#pragma unroll
    for (int mi = 0; mi < 2; mi++) {
        const int r0 = m0 + mb + mi * 16 + g;
        const int r1 = r0 + 8;
        const float s0 = (r0 < M) ? g_dinv[r0] : 0.f;
        const float s1 = (r1 < M) ? g_dinv[r1] : 0.f;
#pragma unroll
        for (int ni = 0; ni < NA; ni++) {
            const int col = nb + ni * 8 + tg * 2;
            if (r0 < M) {
                __half2 o = __floats2half2_rn(acc[mi][ni][0] * s0, acc[mi][ni][1] * s0);
                *(__half2*)&g_h16[(size_t)r0 * N + col] = o;
            }
            if (r1 < M) {
                __half2 o = __floats2half2_rn(acc[mi][ni][2] * s1, acc[mi][ni][3] * s1);
                *(__half2*)&g_h16[(size_t)r1 * N + col] = o;
            }
        }
    }
}

// ---------------- fused gather-aggregate (fp16 payload, fp32 accum) ----------------
// One warp per node, edge loop unrolled 8-deep.
// o[d] = (h16[d] + sum_{s in CSR(d)} h16[s]) * dinv[d] + b

__device__ __forceinline__ void acc_half4(float4& acc, uint2 u) {
    float2 f0 = __half22float2(*reinterpret_cast<__half2*>(&u.x));
    float2 f1 = __half22float2(*reinterpret_cast<__half2*>(&u.y));
    acc.x += f0.x; acc.y += f0.y; acc.z += f1.x; acc.w += f1.y;
}

template<int N, bool TO_OUT>
__global__ void gather_kernel(const float* __restrict__ b, float* __restrict__ out) {
    const int warps_per_block = blockDim.x >> 5;
    const int node = blockIdx.x * warps_per_block + (threadIdx.x >> 5);
    const int lane = threadIdx.x & 31;
    if (node >= N_NODES) return;

    float* __restrict__ o = TO_OUT ? out : (float*)g_agg;
    const float di = g_dinv[node];
    const int beg = g_off[node];
    const int end = beg + g_deg[node] - 1;

    if (N == 128) {
        const int c = lane * 4;
        float4 acc = make_float4(0.f, 0.f, 0.f, 0.f);
        acc_half4(acc, *(const uint2*)&g_h16[(size_t)node * N + c]);
        int e = beg;
        for (; e + 8 <= end; e += 8) {
            int s[8];
#pragma unroll
            for (int k = 0; k < 8; k++) s[k] = g_csr_src[e + k];
            uint2 u[8];
#pragma unroll
            for (int k = 0; k < 8; k++) u[k] = *(const uint2*)&g_h16[(size_t)s[k] * N + c];
#pragma unroll
            for (int k = 0; k < 8; k++) acc_half4(acc, u[k]);
        }
        for (; e < end; e++) {
            int s0 = g_csr_src[e];
            acc_half4(acc, *(const uint2*)&g_h16[(size_t)s0 * N + c]);
        }
        acc.x = acc.x * di + b[c];
        acc.y = acc.y * di + b[c + 1];
        acc.z = acc.z * di + b[c + 2];
        acc.w = acc.w * di + b[c + 3];
        *(float4*)&o[(size_t)node * N + c] = acc;
    } else {
        const int c = lane * 2;
        float2 acc = __half22float2(*(const __half2*)&g_h16[(size_t)node * N + c]);
        int e = beg;
        for (; e + 8 <= end; e += 8) {
            int s[8];
#pragma unroll
            for (int k = 0; k < 8; k++) s[k] = g_csr_src[e + k];
            float2 f[8];
#pragma unroll
            for (int k = 0; k < 8; k++)
                f[k] = __half22float2(*(const __half2*)&g_h16[(size_t)s[k] * N + c]);
#pragma unroll
            for (int k = 0; k < 8; k++) {
                acc.x += f[k].x;
                acc.y += f[k].y;
            }
        }
        for (; e < end; e++) {
            int s0 = g_csr_src[e];
            float2 f0 = __half22float2(*(const __half2*)&g_h16[(size_t)s0 * N + c]);
            acc.x += f0.x; acc.y += f0.y;
        }
        acc.x = acc.x * di + b[c];
        acc.y = acc.y * di + b[c + 1];
        *(float2*)&o[(size_t)node * N + c] = acc;
    }
}

// ---------------- launch ----------------

extern "C" void kernel_launch(void* const* d_in, const int* in_sizes, int n_in,
                              void* d_out, int out_size) {
    const float* x  = (const float*)d_in[0];
    const int* ei   = (const int*)d_in[1];    // int32 (JAX x64 disabled)
    const float* W1 = (const float*)d_in[2];
    const float* b1 = (const float*)d_in[3];
    const float* W2 = (const float*)d_in[4];
    const float* b2 = (const float*)d_in[5];
    const float* W3 = (const float*)d_in[6];
    const float* b3 = (const float*)d_in[7];
    float* out      = (float*)d_out;

    const int* src = ei;
    const int* dst = ei + N_EDGES;

    constexpr int SB = 136;
    constexpr int SMEM_128 = (2 * 64 * SB + 2 * 128 * SB) * 2;  // 104448 -> 2 CTAs/SM
    constexpr int SMEM_64  = (2 * 64 * SB + 2 * 64 * SB) * 2;   // 69632  -> 3 CTAs/SM
    cudaFuncSetAttribute(gemm_mma_kernel<128, false, false, 1>,
                         cudaFuncAttributeMaxDynamicSharedMemorySize, SMEM_128);
    cudaFuncSetAttribute(gemm_mma_kernel<128, true, true, 2>,
                         cudaFuncAttributeMaxDynamicSharedMemorySize, SMEM_128);
    cudaFuncSetAttribute(gemm_mma_kernel<64, true, true, 3>,
                         cudaFuncAttributeMaxDynamicSharedMemorySize, SMEM_64);

    // setup: deg init + presplit all weights (1 launch)
    setup_kernel<<<216, 256>>>(W1, W2, W3);
    deg_count_kernel<<<(N_EDGES / 8 + 255) / 256, 256>>>((const int4*)dst);
    dinv_alloc_kernel<<<(N_NODES + 255) / 256, 256>>>();
    fill_kernel<<<(N_EDGES / 8 + 255) / 256, 256>>>((const int4*)src, (const int4*)dst);

    const int gemm_blocks = (N_NODES + 63) / 64;     // 782
    const int gather_blocks = (N_NODES + 7) / 8;     // 8 warps/block

    // Layer 1
    gemm_mma_kernel<128, false, false, 1><<<gemm_blocks, 256, SMEM_128>>>(x, N_NODES);
    gather_kernel<128, false><<<gather_blocks, 256>>>(b1, nullptr);

    // Layer 2
    gemm_mma_kernel<128, true, true, 2><<<gemm_blocks, 256, SMEM_128>>>(nullptr, N_NODES);
    gather_kernel<128, false><<<gather_blocks, 256>>>(b2, nullptr);

    // Layer 3 (N=64) -> d_out
    gemm_mma_kernel<64, true, true, 3><<<gemm_blocks, 256, SMEM_64>>>(nullptr, N_NODES);
    gather_kernel<64, true><<<gather_blocks, 256>>>(b3, out);
}

// round 16
// speedup vs baseline: 1.0491x; 1.0491x over previous
#include <cuda_runtime.h>
#include <cuda_bf16.h>
#include <cuda_fp16.h>
#include <cstdint>

#define N_NODES 50000
#define N_EDGES 800000

// Scratch (__device__ globals; no allocation). NEVER pass these from host code:
// on GB300 (HMM/ATS) the host shadow symbol is GPU-dereferenceable and the kernel
// silently reads host memory over C2C (Round 9: 170->477us regression).
__device__ __half g_h16[N_NODES * 128];  // GEMM output per layer, dinv-scaled, fp16
__device__ float g_agg[N_NODES * 128];   // aggregation output (layers 1,2), fp32
__device__ int   g_deg[N_NODES];
__device__ float g_dinv[N_NODES];
__device__ int   g_off[N_NODES];         // CSR segment start (by dst; unordered alloc)
__device__ int   g_cursor[N_NODES];      // fill cursors
__device__ int   g_csr_src[N_EDGES];     // src ids grouped by dst
__device__ int   g_total;                // bump allocator
// Presplit weights, n-major: WT[n*128 + k]
__device__ __nv_bfloat16 g_W1hi[128 * 128], g_W1lo[128 * 128];
__device__ __nv_bfloat16 g_W2hi[128 * 128], g_W2lo[128 * 128];
__device__ __nv_bfloat16 g_W3hi[64 * 128],  g_W3lo[64 * 128];

template<int LAYER>
__device__ __forceinline__ __nv_bfloat16* w_hi() {
    return LAYER == 1 ? g_W1hi : (LAYER == 2 ? g_W2hi : g_W3hi);
}
template<int LAYER>
__device__ __forceinline__ __nv_bfloat16* w_lo() {
    return LAYER == 1 ? g_W1lo : (LAYER == 2 ? g_W2lo : g_W3lo);
}

// ---------------- fp32 -> bf16 hi/lo split helpers ----------------

__device__ __forceinline__ void split8(const float* v, uint4& hi, uint4& lo) {
    uint32_t h[4], l[4];
#pragma unroll
    for (int j = 0; j < 4; j++) {
        __nv_bfloat16 h0 = __float2bfloat16(v[2 * j]);
        __nv_bfloat16 h1 = __float2bfloat16(v[2 * j + 1]);
        float f0 = __bfloat162float(h0), f1 = __bfloat162float(h1);
        __nv_bfloat162 hh = __halves2bfloat162(h0, h1);
        __nv_bfloat162 ll = __halves2bfloat162(__float2bfloat16(v[2 * j] - f0),
                                               __float2bfloat16(v[2 * j + 1] - f1));
        h[j] = *reinterpret_cast<uint32_t*>(&hh);
        l[j] = *reinterpret_cast<uint32_t*>(&ll);
    }
    hi = make_uint4(h[0], h[1], h[2], h[3]);
    lo = make_uint4(l[0], l[1], l[2], l[3]);
}

template<int N>
__device__ __forceinline__ void wsplit_work(const float* __restrict__ W,
                                            __nv_bfloat16* hi, __nv_bfloat16* lo, int idx) {
    int n = idx % N;
    int kg = idx / N;
    float v[8];
#pragma unroll
    for (int j = 0; j < 8; j++) v[j] = W[(size_t)(kg * 8 + j) * N + n];
    uint4 h, l;
    split8(v, h, l);
    *(uint4*)&hi[n * 128 + kg * 8] = h;
    *(uint4*)&lo[n * 128 + kg * 8] = l;
}

// ---------------- fused setup: deg init + weight presplit (one launch) ----------------

__global__ void setup_kernel(const float* __restrict__ W1, const float* __restrict__ W2,
                             const float* __restrict__ W3) {
    const int bid = blockIdx.x;
    const int tid = threadIdx.x;
    if (bid < 196) {
        int i = bid * 256 + tid;
        if (i == 0) g_total = 0;
        if (i < N_NODES) g_deg[i] = 1;   // self loop
    } else {
        int idx = (bid - 196) * 256 + tid;          // 0..5119
        if (idx < 2048) {
            wsplit_work<128>(W1, g_W1hi, g_W1lo, idx);
        } else if (idx < 4096) {
            wsplit_work<128>(W2, g_W2hi, g_W2lo, idx - 2048);
        } else if (idx < 5120) {
            wsplit_work<64>(W3, g_W3hi, g_W3lo, idx - 4096);
        }
    }
}

// ---------------- degree count: 4 edges/thread ----------------

__global__ void deg_count_kernel(const int4* __restrict__ dst4) {
    int i = blockIdx.x * blockDim.x + threadIdx.x;
    if (i < N_EDGES / 4) {
        int4 d = dst4[i];
        atomicAdd(&g_deg[d.x], 1);
        atomicAdd(&g_deg[d.y], 1);
        atomicAdd(&g_deg[d.z], 1);
        atomicAdd(&g_deg[d.w], 1);
    }
}

// dinv + CSR segment allocation (merged)
__global__ void dinv_alloc_kernel() {
    int i = blockIdx.x * blockDim.x + threadIdx.x;
    int lane = threadIdx.x & 31;
    int deg = (i < N_NODES) ? g_deg[i] : 1;
    if (i < N_NODES) g_dinv[i] = rsqrtf((float)deg);
    int cnt = (i < N_NODES) ? (deg - 1) : 0;
    int incl = cnt;
#pragma unroll
    for (int off = 1; off < 32; off <<= 1) {
        int t = __shfl_up_sync(0xffffffffu, incl, off);
        if (lane >= off) incl += t;
    }
    int total = __shfl_sync(0xffffffffu, incl, 31);
    int base = 0;
    if (lane == 0) base = atomicAdd(&g_total, total);
    base = __shfl_sync(0xffffffffu, base, 0);
    if (i < N_NODES) {
        int beg = base + incl - cnt;
        g_off[i] = beg;
        g_cursor[i] = beg;
    }
}

// CSR fill: 4 edges/thread, independent atomic chains for MLP
__global__ void fill_kernel(const int4* __restrict__ src4, const int4* __restrict__ dst4) {
    int i = blockIdx.x * blockDim.x + threadIdx.x;
    if (i < N_EDGES / 4) {
        int4 s = src4[i];
        int4 d = dst4[i];
        int p0 = atomicAdd(&g_cursor[d.x], 1);
        int p1 = atomicAdd(&g_cursor[d.y], 1);
        int p2 = atomicAdd(&g_cursor[d.z], 1);
        int p3 = atomicAdd(&g_cursor[d.w], 1);
        g_csr_src[p0] = s.x;
        g_csr_src[p1] = s.y;
        g_csr_src[p2] = s.z;
        g_csr_src[p3] = s.w;
    }
}

// ================= bf16x3 mma.sync GEMM =================
// g_h16[M,N] = fp16( ( act(X[M,128]) @ W[128,N] ) * dinv[row] )

__device__ __forceinline__ uint32_t smem_u32(const void* p) {
    return (uint32_t)__cvta_generic_to_shared(p);
}

__device__ __forceinline__ void ldsm4(uint32_t* r, uint32_t addr) {
    asm volatile("ldmatrix.sync.aligned.m8n8.x4.shared.b16 {%0,%1,%2,%3}, [%4];"
                 : "=r"(r[0]), "=r"(r[1]), "=r"(r[2]), "=r"(r[3]) : "r"(addr));
}

__device__ __forceinline__ void mma16816(float* d, const uint32_t* a,
                                         uint32_t b0, uint32_t b1) {
    asm volatile(
        "mma.sync.aligned.m16n8k16.row.col.f32.bf16.bf16.f32 "
        "{%0,%1,%2,%3}, {%4,%5,%6,%7}, {%8,%9}, {%0,%1,%2,%3};"
        : "+f"(d[0]), "+f"(d[1]), "+f"(d[2]), "+f"(d[3])
        : "r"(a[0]), "r"(a[1]), "r"(a[2]), "r"(a[3]), "r"(b0), "r"(b1));
}

// Block: 128(M) x N, K=128 resident. 8 warps in 4x2; warp tile 32 x N/2.
template<int N, bool RELU, bool FROM_AGG, int LAYER>
__global__ void __launch_bounds__(256) gemm_mma_kernel(const float* __restrict__ X, int M) {
    constexpr int K = 128, BM = 128, SB = 136;
    constexpr int A_ELE = BM * SB;
    constexpr int B_ELE = N * SB;
    constexpr int NA = N / 16;

    extern __shared__ __nv_bfloat16 sm[];
    __nv_bfloat16* Ahi = sm;
    __nv_bfloat16* Alo = sm + A_ELE;
    __nv_bfloat16* Bhi = sm + 2 * A_ELE;
    __nv_bfloat16* Blo = sm + 2 * A_ELE + B_ELE;

    const float* __restrict__ Xp = FROM_AGG ? (const float*)g_agg : X;
    const __nv_bfloat16* __restrict__ WThi = w_hi<LAYER>();
    const __nv_bfloat16* __restrict__ WTlo = w_lo<LAYER>();
    const int tid = threadIdx.x;
    const int m0 = blockIdx.x * BM;

    // ---- copy presplit W into smem ----
#pragma unroll
    for (int i = tid; i < N * 16; i += 256) {
        int n = i >> 4;
        int k0 = (i & 15) * 8;
        *(uint4*)&Bhi[n * SB + k0] = *(const uint4*)&WThi[n * 128 + k0];
        *(uint4*)&Blo[n * SB + k0] = *(const uint4*)&WTlo[n * 128 + k0];
    }

    // ---- load + split X: thread = (row, half-row of 64) ----
    {
        const int row = tid >> 1;
        const int kh = (tid & 1) * 64;
        const int gm = m0 + row;
        float v[8];
#pragma unroll
        for (int c0 = 0; c0 < 64; c0 += 8) {
            if (gm < M) {
                float4 a = *(const float4*)&Xp[(size_t)gm * K + kh + c0];
                float4 b = *(const float4*)&Xp[(size_t)gm * K + kh + c0 + 4];
                v[0] = a.x; v[1] = a.y; v[2] = a.z; v[3] = a.w;
                v[4] = b.x; v[5] = b.y; v[6] = b.z; v[7] = b.w;
                if (RELU) {
#pragma unroll
                    for (int j = 0; j < 8; j++) v[j] = fmaxf(v[j], 0.f);
                }
            } else {
#pragma unroll
                for (int j = 0; j < 8; j++) v[j] = 0.f;
            }
            uint4 hi, lo;
            split8(v, hi, lo);
            *(uint4*)&Ahi[row * SB + kh + c0] = hi;
            *(uint4*)&Alo[row * SB + kh + c0] = lo;
        }
    }
    __syncthreads();

    const uint32_t aHi = smem_u32(Ahi), aLo = smem_u32(Alo);
    const uint32_t bHi = smem_u32(Bhi), bLo = smem_u32(Blo);
    const int wid = tid >> 5, lane = tid & 31;
    const int mb = (wid & 3) * 32;
    const int nb = (wid >> 2) * (N / 2);

    float acc[2][NA][4];
#pragma unroll
    for (int mi = 0; mi < 2; mi++)
#pragma unroll
        for (int ni = 0; ni < NA; ni++)
#pragma unroll
            for (int j = 0; j < 4; j++) acc[mi][ni][j] = 0.f;

    const int l3 = lane >> 3;
    const uint32_t offA = (uint32_t)((mb + (lane & 15)) * SB + ((lane >> 4) << 3)) * 2;
    const uint32_t offB = (uint32_t)((nb + ((l3 >> 1) << 3) + (lane & 7)) * SB + ((l3 & 1) << 3)) * 2;

#pragma unroll
    for (int ks = 0; ks < 8; ks++) {
        const uint32_t kofs = (uint32_t)(ks * 16 * 2);
        uint32_t ah[2][4], al[2][4];
        ldsm4(ah[0], aHi + offA + kofs);
        ldsm4(ah[1], aHi + offA + kofs + 16 * SB * 2);
        ldsm4(al[0], aLo + offA + kofs);
        ldsm4(al[1], aLo + offA + kofs + 16 * SB * 2);

        uint32_t bh[NA][2], bl[NA][2];
#pragma unroll
        for (int nq = 0; nq < NA / 2; nq++) {
            uint32_t r[4];
            ldsm4(r, bHi + offB + kofs + nq * 16 * SB * 2);
            bh[2 * nq][0] = r[0]; bh[2 * nq][1] = r[1];
            bh[2 * nq + 1][0] = r[2]; bh[2 * nq + 1][1] = r[3];
            ldsm4(r, bLo + offB + kofs + nq * 16 * SB * 2);
            bl[2 * nq][0] = r[0]; bl[2 * nq][1] = r[1];
            bl[2 * nq + 1][0] = r[2]; bl[2 * nq + 1][1] = r[3];
        }

#pragma unroll
        for (int mi = 0; mi < 2; mi++)
#pragma unroll
            for (int ni = 0; ni < NA; ni++) {
                mma16816(acc[mi][ni], ah[mi], bh[ni][0], bh[ni][1]);
                mma16816(acc[mi][ni], ah[mi], bl[ni][0], bl[ni][1]);
                mma16816(acc[mi][ni], al[mi], bh[ni][0], bh[ni][1]);
            }
    }

    // ---- epilogue: scale by dinv[row], convert fp16, store ----
    const int g = lane >> 2, tg = lane & 3;
#pragma unroll
    for (int mi = 0; mi < 2; mi++) {
        const int r0 = m0 + mb + mi * 16 + g;
        const int r1 = r0 + 8;
        const float s0 = (r0 < M) ? g_dinv[r0] : 0.f;
        const float s1 = (r1 < M) ? g_dinv[r1] : 0.f;
#pragma unroll
        for (int ni = 0; ni < NA; ni++) {
            const int col = nb + ni * 8 + tg * 2;
            if (r0 < M) {
                __half2 o = __floats2half2_rn(acc[mi][ni][0] * s0, acc[mi][ni][1] * s0);
                *(__half2*)&g_h16[(size_t)r0 * N + col] = o;
            }
            if (r1 < M) {
                __half2 o = __floats2half2_rn(acc[mi][ni][2] * s1, acc[mi][ni][3] * s1);
                *(__half2*)&g_h16[(size_t)r1 * N + col] = o;
            }
        }
    }
}

// ---------------- fused gather-aggregate (fp16 payload, fp32 accum) ----------------
// One warp per node, edge loop unrolled 8-deep.
// o[d] = (h16[d] + sum_{s in CSR(d)} h16[s]) * dinv[d] + b

__device__ __forceinline__ void acc_half4(float4& acc, uint2 u) {
    float2 f0 = __half22float2(*reinterpret_cast<__half2*>(&u.x));
    float2 f1 = __half22float2(*reinterpret_cast<__half2*>(&u.y));
    acc.x += f0.x; acc.y += f0.y; acc.z += f1.x; acc.w += f1.y;
}

template<int N, bool TO_OUT>
__global__ void gather_kernel(const float* __restrict__ b, float* __restrict__ out) {
    const int warps_per_block = blockDim.x >> 5;
    const int node = blockIdx.x * warps_per_block + (threadIdx.x >> 5);
    const int lane = threadIdx.x & 31;
    if (node >= N_NODES) return;

    float* __restrict__ o = TO_OUT ? out : (float*)g_agg;
    const float di = g_dinv[node];
    const int beg = g_off[node];
    const int end = beg + g_deg[node] - 1;

    if (N == 128) {
        const int c = lane * 4;
        float4 acc = make_float4(0.f, 0.f, 0.f, 0.f);
        acc_half4(acc, *(const uint2*)&g_h16[(size_t)node * N + c]);
        int e = beg;
        for (; e + 8 <= end; e += 8) {
            int s[8];
#pragma unroll
            for (int k = 0; k < 8; k++) s[k] = g_csr_src[e + k];
            uint2 u[8];
#pragma unroll
            for (int k = 0; k < 8; k++) u[k] = *(const uint2*)&g_h16[(size_t)s[k] * N + c];
#pragma unroll
            for (int k = 0; k < 8; k++) acc_half4(acc, u[k]);
        }
        for (; e < end; e++) {
            int s0 = g_csr_src[e];
            acc_half4(acc, *(const uint2*)&g_h16[(size_t)s0 * N + c]);
        }
        acc.x = acc.x * di + b[c];
        acc.y = acc.y * di + b[c + 1];
        acc.z = acc.z * di + b[c + 2];
        acc.w = acc.w * di + b[c + 3];
        *(float4*)&o[(size_t)node * N + c] = acc;
    } else {
        const int c = lane * 2;
        float2 acc = __half22float2(*(const __half2*)&g_h16[(size_t)node * N + c]);
        int e = beg;
        for (; e + 8 <= end; e += 8) {
            int s[8];
#pragma unroll
            for (int k = 0; k < 8; k++) s[k] = g_csr_src[e + k];
            float2 f[8];
#pragma unroll
            for (int k = 0; k < 8; k++)
                f[k] = __half22float2(*(const __half2*)&g_h16[(size_t)s[k] * N + c]);
#pragma unroll
            for (int k = 0; k < 8; k++) {
                acc.x += f[k].x;
                acc.y += f[k].y;
            }
        }
        for (; e < end; e++) {
            int s0 = g_csr_src[e];
            float2 f0 = __half22float2(*(const __half2*)&g_h16[(size_t)s0 * N + c]);
            acc.x += f0.x; acc.y += f0.y;
        }
        acc.x = acc.x * di + b[c];
        acc.y = acc.y * di + b[c + 1];
        *(float2*)&o[(size_t)node * N + c] = acc;
    }
}

// ---------------- launch ----------------

extern "C" void kernel_launch(void* const* d_in, const int* in_sizes, int n_in,
                              void* d_out, int out_size) {
    const float* x  = (const float*)d_in[0];
    const int* ei   = (const int*)d_in[1];    // int32 (JAX x64 disabled)
    const float* W1 = (const float*)d_in[2];
    const float* b1 = (const float*)d_in[3];
    const float* W2 = (const float*)d_in[4];
    const float* b2 = (const float*)d_in[5];
    const float* W3 = (const float*)d_in[6];
    const float* b3 = (const float*)d_in[7];
    float* out      = (float*)d_out;

    const int* src = ei;
    const int* dst = ei + N_EDGES;

    constexpr int SB = 136;
    constexpr int SMEM_128 = (2 * 128 * SB + 2 * 128 * SB) * 2;  // 139264
    constexpr int SMEM_64  = (2 * 128 * SB + 2 * 64 * SB) * 2;   // 104448
    cudaFuncSetAttribute(gemm_mma_kernel<128, false, false, 1>,
                         cudaFuncAttributeMaxDynamicSharedMemorySize, SMEM_128);
    cudaFuncSetAttribute(gemm_mma_kernel<128, true, true, 2>,
                         cudaFuncAttributeMaxDynamicSharedMemorySize, SMEM_128);
    cudaFuncSetAttribute(gemm_mma_kernel<64, true, true, 3>,
                         cudaFuncAttributeMaxDynamicSharedMemorySize, SMEM_64);

    // Side stream + events for fork/join (created once; reused every call)
    static cudaStream_t s2 = nullptr;
    static cudaEvent_t evFork = nullptr, evJoin = nullptr;
    if (s2 == nullptr) {
        cudaStreamCreateWithFlags(&s2, cudaStreamNonBlocking);
        cudaEventCreateWithFlags(&evFork, cudaEventDisableTiming);
        cudaEventCreateWithFlags(&evJoin, cudaEventDisableTiming);
    }

    // setup: deg init + presplit all weights (1 launch)
    setup_kernel<<<216, 256>>>(W1, W2, W3);
    deg_count_kernel<<<(N_EDGES / 4 + 255) / 256, 256>>>((const int4*)dst);
    dinv_alloc_kernel<<<(N_NODES + 255) / 256, 256>>>();

    const int gemm_blocks = (N_NODES + 127) / 128;   // 391
    const int gather_blocks = (N_NODES + 7) / 8;     // 8 warps/block

    // Fork: CSR fill (side stream) runs concurrently with layer-1 GEMM (main stream).
    cudaEventRecord(evFork, 0);
    cudaStreamWaitEvent(s2, evFork, 0);
    fill_kernel<<<(N_EDGES / 4 + 255) / 256, 256, 0, s2>>>((const int4*)src, (const int4*)dst);
    cudaEventRecord(evJoin, s2);

    gemm_mma_kernel<128, false, false, 1><<<gemm_blocks, 256, SMEM_128>>>(x, N_NODES);

    // Join: gather needs both the CSR and the GEMM output.
    cudaStreamWaitEvent(0, evJoin, 0);
    gather_kernel<128, false><<<gather_blocks, 256>>>(b1, nullptr);

    // Layer 2
    gemm_mma_kernel<128, true, true, 2><<<gemm_blocks, 256, SMEM_128>>>(nullptr, N_NODES);
    gather_kernel<128, false><<<gather_blocks, 256>>>(b2, nullptr);

    // Layer 3 (N=64) -> d_out
    gemm_mma_kernel<64, true, true, 3><<<gemm_blocks, 256, SMEM_64>>>(nullptr, N_NODES);
    gather_kernel<64, true><<<gather_blocks, 256>>>(b3, out);
}